// round 1
// baseline (speedup 1.0000x reference)
#include <cuda_runtime.h>

// MatrixMemory: y = state @ query (per-batch GEMV), dM = d_out ⊗ key (per-batch outer)
// B=2048, DK=DV=256. Pure streaming: 512MiB read (state) + 512MiB write (dM).
//
// Layout: out = [ y (B*DV floats) | dM (B*DV*DK floats) ]
//
// One warp per (b, v) row:
//   - dot(state[b][v][:], q[b][:])  -> y[b*DV + v]
//   - dM[b][v][k] = d_out[b][v] * key[b][k]
// q and k cached in shared memory per block (8 rows share the same batch).

#define B_  2048
#define DK_ 256
#define DV_ 256

__global__ __launch_bounds__(256, 8)
void mm_fused_kernel(const float4* __restrict__ state,   // [B, DV, DK] as float4
                     const float*  __restrict__ query,   // [B, DK]
                     const float*  __restrict__ keyv,    // [B, DK]
                     const float*  __restrict__ dout,    // [B, DV]
                     float*        __restrict__ y,       // [B, DV]
                     float4*       __restrict__ dM)      // [B, DV, DK] as float4
{
    const int b     = blockIdx.x >> 5;          // 32 blocks per batch
    const int vbase = (blockIdx.x & 31) << 3;   // 8 v-rows per block

    __shared__ float4 sq[64];   // query[b] as 64 float4
    __shared__ float4 sk[64];   // key[b]   as 64 float4

    const int tid = threadIdx.x;
    if (tid < 64) {
        sq[tid] = reinterpret_cast<const float4*>(query + (long)b * DK_)[tid];
    } else if (tid < 128) {
        sk[tid - 64] = reinterpret_cast<const float4*>(keyv + (long)b * DK_)[tid - 64];
    }
    __syncthreads();

    const int w    = tid >> 5;
    const int lane = tid & 31;
    const int v    = vbase + w;
    const long row = (long)b * DV_ + v;          // global row index (B*DV rows)

    // ---- read state row (1KB) with streaming hint, dot with q ----
    const float4* srow = state + row * (DK_ / 4);
    float4 a0 = __ldcs(srow + lane);             // k = lane*4 .. lane*4+3
    float4 a1 = __ldcs(srow + 32 + lane);        // k = 128 + lane*4 ..

    float4 q0 = sq[lane];
    float4 q1 = sq[lane + 32];

    float s = a0.x * q0.x + a0.y * q0.y + a0.z * q0.z + a0.w * q0.w
            + a1.x * q1.x + a1.y * q1.y + a1.z * q1.z + a1.w * q1.w;

    // warp reduce
    #pragma unroll
    for (int off = 16; off > 0; off >>= 1)
        s += __shfl_xor_sync(0xFFFFFFFFu, s, off);

    // ---- outer-product row write (1KB) with streaming hint ----
    const float dov = __ldg(dout + row);         // scalar, broadcast within warp

    float4 k0 = sk[lane];
    float4 k1 = sk[lane + 32];
    float4 o0 = make_float4(dov * k0.x, dov * k0.y, dov * k0.z, dov * k0.w);
    float4 o1 = make_float4(dov * k1.x, dov * k1.y, dov * k1.z, dov * k1.w);

    float4* drow = dM + row * (DK_ / 4);
    __stcs(drow + lane,      o0);
    __stcs(drow + lane + 32, o1);

    if (lane == 0) y[row] = s;
}

extern "C" void kernel_launch(void* const* d_in, const int* in_sizes, int n_in,
                              void* d_out, int out_size)
{
    const float4* state = (const float4*)d_in[0];
    const float*  query = (const float*) d_in[1];
    const float*  keyv  = (const float*) d_in[2];
    const float*  dov   = (const float*) d_in[3];

    float* out = (float*)d_out;
    float*  y  = out;                              // [B, DV]
    float4* dM = (float4*)(out + (long)B_ * DV_);  // [B, DV, DK]

    dim3 grid(B_ * 32);   // 32 blocks per batch, 8 warps each -> 8 rows/block
    dim3 block(256);
    mm_fused_kernel<<<grid, block>>>(state, query, keyv, dov, y, dM);
}